// round 3
// baseline (speedup 1.0000x reference)
#include <cuda_runtime.h>
#include <cstdint>
#include <math.h>

// Problem dims
#define M_DIM 16
#define VN    8192
#define DIN   512
#define DOUT  512
#define ROWS  (M_DIM * VN)              // 131072 flattened (m,v) rows
#define NPER  (VN * DIN)                // 4194304 elements per m-slice
#define NPER4 (NPER / 4)                // 1048576 float4 per m-slice

#define GRAM_CTAS   1024
#define PART_STRIDE 272                 // 256 G partials + 16 sq partials

// -------------------- scratch (device globals; no allocation) --------------------
__device__ float g_Q[(size_t)ROWS * DOUT];    // Q, later reused as Y (mixed X)
__device__ float g_K[(size_t)ROWS * DOUT];
__device__ float g_part[GRAM_CTAS * PART_STRIDE];
__device__ float g_P[256];
__device__ float g_csum[16];

// -------------------- helpers --------------------
__device__ __forceinline__ uint32_t f2tf(float f) {
    uint32_t u;
    asm("cvt.rna.tf32.f32 %0, %1;" : "=r"(u) : "f"(f));
    return u;
}

__device__ __forceinline__ void mma_tf32(float c[4], const uint32_t a[4],
                                         uint32_t b0, uint32_t b1) {
    asm volatile(
        "mma.sync.aligned.m16n8k8.row.col.f32.tf32.tf32.f32 "
        "{%0,%1,%2,%3}, {%4,%5,%6,%7}, {%8,%9}, {%0,%1,%2,%3};\n"
        : "+f"(c[0]), "+f"(c[1]), "+f"(c[2]), "+f"(c[3])
        : "r"(a[0]), "r"(a[1]), "r"(a[2]), "r"(a[3]), "r"(b0), "r"(b1));
}

// -------------------- TF32 GEMM: C[r,d] = sum_k A[r,k]*W[d,k] + s*bias[d] ----------
// mode 0: A=Aext (X), C=g_Q, s=1
// mode 1: A=Aext (X), C=g_K, s=1
// mode 2: A=g_Q (Y),  C=Cext(out), s=g_csum[r/8192]
// Tiles: 128x128x32, 256 threads (8 warps: 4(M) x 2(N)), warp = 32x64.
__global__ void __launch_bounds__(256) gemm_tf32(
    const float* __restrict__ Aext, const float* __restrict__ W,
    const float* __restrict__ bias, int mode, float* __restrict__ Cext)
{
    __shared__ uint32_t As[128 * 36];
    __shared__ uint32_t Bs[128 * 36];

    const float* A = (mode == 2) ? (const float*)g_Q : Aext;
    float*       C = (mode == 0) ? g_Q : ((mode == 1) ? g_K : Cext);

    const int tid  = threadIdx.x;
    const int lane = tid & 31;
    const int wid  = tid >> 5;
    const int gid  = lane >> 2;   // 0..7
    const int tig  = lane & 3;    // 0..3
    const int wm   = wid & 3;     // warp row  (32 rows)
    const int wn   = wid >> 2;    // warp col  (64 cols)
    const int m0   = blockIdx.y * 128;
    const int n0   = blockIdx.x * 128;

    float acc[2][8][4];
#pragma unroll
    for (int a = 0; a < 2; a++)
#pragma unroll
        for (int b = 0; b < 8; b++)
#pragma unroll
            for (int c = 0; c < 4; c++) acc[a][b][c] = 0.f;

    for (int kt = 0; kt < DIN; kt += 32) {
#pragma unroll
        for (int it = 0; it < 4; ++it) {
            int idx = tid + it * 256;      // 0..1023 float4 slots
            int r   = idx >> 3;            // 0..127
            int c4  = (idx & 7) << 2;      // 0,4,...,28
            float4 va = *(const float4*)(A + (size_t)(m0 + r) * DIN + kt + c4);
            float4 vb = *(const float4*)(W + (size_t)(n0 + r) * DIN + kt + c4);
            uint4 ua = make_uint4(f2tf(va.x), f2tf(va.y), f2tf(va.z), f2tf(va.w));
            uint4 ub = make_uint4(f2tf(vb.x), f2tf(vb.y), f2tf(vb.z), f2tf(vb.w));
            *(uint4*)&As[r * 36 + c4] = ua;
            *(uint4*)&Bs[r * 36 + c4] = ub;
        }
        __syncthreads();
#pragma unroll
        for (int ks = 0; ks < 4; ++ks) {
            const int kb = ks * 8;
            uint32_t af[2][4];
#pragma unroll
            for (int mf = 0; mf < 2; ++mf) {
                int rb = wm * 32 + mf * 16;
                af[mf][0] = As[(rb + gid)     * 36 + kb + tig];
                af[mf][1] = As[(rb + gid + 8) * 36 + kb + tig];
                af[mf][2] = As[(rb + gid)     * 36 + kb + tig + 4];
                af[mf][3] = As[(rb + gid + 8) * 36 + kb + tig + 4];
            }
#pragma unroll
            for (int nf = 0; nf < 8; ++nf) {
                int nb = wn * 64 + nf * 8;
                uint32_t b0 = Bs[(nb + gid) * 36 + kb + tig];
                uint32_t b1 = Bs[(nb + gid) * 36 + kb + tig + 4];
                mma_tf32(acc[0][nf], af[0], b0, b1);
                mma_tf32(acc[1][nf], af[1], b0, b1);
            }
        }
        __syncthreads();
    }

    float s = 1.f;
    if (mode == 2) s = g_csum[m0 >> 13];   // 8192 rows per j-block; tile never straddles
#pragma unroll
    for (int nf = 0; nf < 8; ++nf) {
        int col = n0 + wn * 64 + nf * 8 + tig * 2;
        float b0 = s * bias[col];
        float b1 = s * bias[col + 1];
#pragma unroll
        for (int mf = 0; mf < 2; ++mf) {
            int r0 = m0 + wm * 32 + mf * 16 + gid;
            *(float2*)(C + (size_t)r0 * DOUT + col) =
                make_float2(acc[mf][nf][0] + b0, acc[mf][nf][1] + b1);
            *(float2*)(C + (size_t)(r0 + 8) * DOUT + col) =
                make_float2(acc[mf][nf][2] + b0, acc[mf][nf][3] + b1);
        }
    }
}

// -------------------- Gram + squared norms (fp32, deterministic partials) ----------
// G_raw[i,j] = sum_n Q[i][n]*K[j][n]; sq[i] = sum_n Q[i][n]^2
// Thread (i,j) = (tid>>4, tid&15). Each CTA covers 4096 n's in 16 smem-staged chunks.
__global__ void __launch_bounds__(256) gram_kernel()
{
    __shared__ float4 Qs[16 * 64];
    __shared__ float4 Ks[16 * 64];
    const int tid = threadIdx.x;
    const int i = tid >> 4, j = tid & 15;
    const float4* Q4 = (const float4*)g_Q;
    const float4* K4 = (const float4*)g_K;

    float accG = 0.f, accS = 0.f;
    size_t base4 = (size_t)blockIdx.x * 1024;   // 4096 floats / 4

    for (int sc = 0; sc < 16; ++sc) {
        size_t nb4 = base4 + (size_t)sc * 64;
        __syncthreads();
#pragma unroll
        for (int it = 0; it < 4; ++it) {
            int idx = tid + it * 256;
            int m = idx >> 6, c = idx & 63;
            Qs[m * 64 + c] = Q4[(size_t)m * NPER4 + nb4 + c];
            Ks[m * 64 + c] = K4[(size_t)m * NPER4 + nb4 + c];
        }
        __syncthreads();
#pragma unroll 4
        for (int c = 0; c < 64; ++c) {
            float4 q = Qs[i * 64 + c];
            float4 k = Ks[j * 64 + c];
            accG += q.x * k.x + q.y * k.y + q.z * k.z + q.w * k.w;
            if (i == j) accS += q.x * q.x + q.y * q.y + q.z * q.z + q.w * q.w;
        }
    }
    g_part[blockIdx.x * PART_STRIDE + tid] = accG;
    if (i == j) g_part[blockIdx.x * PART_STRIDE + 256 + i] = accS;
}

// -------------------- finalize: fro, sigmoid, multi_projection, P, colsums ---------
__global__ void __launch_bounds__(256) finalize_kernel()
{
    __shared__ float Am[256], T[256];
    __shared__ float fro[16], m0s[16], s0s[16], m1s[16], s1s[16], red[16], red2[16];
    const int tid = threadIdx.x;
    const int i = tid >> 4, j = tid & 15;

    // reduce deterministic partials
    float g = 0.f;
    for (int c = 0; c < GRAM_CTAS; ++c) g += g_part[c * PART_STRIDE + tid];
    if (tid < 16) {
        float s = 0.f;
        for (int c = 0; c < GRAM_CTAS; ++c) s += g_part[c * PART_STRIDE + 256 + tid];
        fro[tid] = sqrtf(s);
    }
    __syncthreads();

    // G = sigmoid(G_raw / fro_i)   (nq == 1 analytically)
    float p0 = 1.f / (1.f + expf(-g / fro[i]));
    Am[tid] = p0;
    __syncthreads();

    // dual softmax stats
    if (tid < 16) {
        float m = -1e30f;
        for (int k = 0; k < 16; ++k) m = fmaxf(m, Am[k * 16 + tid]);   // over i (col tid)
        float s = 0.f;
        for (int k = 0; k < 16; ++k) s += expf(Am[k * 16 + tid] - m);
        m0s[tid] = m; s0s[tid] = s;
        float m1 = -1e30f;
        for (int k = 0; k < 16; ++k) m1 = fmaxf(m1, Am[tid * 16 + k]); // over j (row tid)
        float s1 = 0.f;
        for (int k = 0; k < 16; ++k) s1 += expf(Am[tid * 16 + k] - m1);
        m1s[tid] = m1; s1s[tid] = s1;
    }
    __syncthreads();

    float p = 0.5f * (expf(p0 - m0s[j]) / s0s[j] + expf(p0 - m1s[i]) / s1s[i]);

    // 10 iterations of projection_p
    for (int it = 0; it < 10; ++it) {
        float p1 = fmaxf(p, 0.f);
        T[tid] = p1;
        __syncthreads();
        if (tid < 16) {            // row sums (axis=1, over j)
            float s = 0.f;
            for (int k = 0; k < 16; ++k) s += T[tid * 16 + k];
            red[tid] = (s - 1.f) * (1.f / 16.f);
        }
        __syncthreads();
        float p2 = p1 - red[i];
        T[tid] = p2;
        __syncthreads();
        if (tid < 16) {            // col sums (axis=0, over i)
            float s = 0.f;
            for (int k = 0; k < 16; ++k) s += T[k * 16 + tid];
            red2[tid] = (s - 1.f) * (1.f / 16.f);
        }
        __syncthreads();
        p = p2 - red2[j];
        __syncthreads();
    }

    g_P[tid] = p;
    T[tid] = p;
    __syncthreads();
    if (tid < 16) {                // colsum_j = sum_i P[i,j] (bias weight for final)
        float s = 0.f;
        for (int k = 0; k < 16; ++k) s += T[k * 16 + tid];
        g_csum[tid] = s;
    }
}

// -------------------- mix: Y[j] = sum_i P[i,j] * X[i]  (into g_Q) ------------------
__global__ void __launch_bounds__(256) mix_kernel(const float* __restrict__ X)
{
    __shared__ float Ps[256];
    Ps[threadIdx.x] = g_P[threadIdx.x];
    __syncthreads();

    size_t n4 = (size_t)blockIdx.x * 256 + threadIdx.x;   // 0..NPER4-1
    const float4* X4 = (const float4*)X;
    float4* Y4 = (float4*)g_Q;

    float4 x[16];
#pragma unroll
    for (int i = 0; i < 16; ++i) x[i] = X4[(size_t)i * NPER4 + n4];
#pragma unroll
    for (int jj = 0; jj < 16; ++jj) {
        float4 y = make_float4(0.f, 0.f, 0.f, 0.f);
#pragma unroll
        for (int i = 0; i < 16; ++i) {
            float pv = Ps[i * 16 + jj];
            y.x += pv * x[i].x; y.y += pv * x[i].y;
            y.z += pv * x[i].z; y.w += pv * x[i].w;
        }
        Y4[(size_t)jj * NPER4 + n4] = y;
    }
}

// -------------------- launch --------------------
extern "C" void kernel_launch(void* const* d_in, const int* in_sizes, int n_in,
                              void* d_out, int out_size)
{
    const float* X   = (const float*)d_in[0];
    const float* WQw = (const float*)d_in[1];
    const float* WQb = (const float*)d_in[2];
    const float* WKw = (const float*)d_in[3];
    const float* WKb = (const float*)d_in[4];
    const float* WVw = (const float*)d_in[5];
    const float* WVb = (const float*)d_in[6];
    float* out = (float*)d_out;

    dim3 ggrid(DOUT / 128, ROWS / 128);   // (4, 1024)

    // Pass 1: Q and K projections (tf32 tensor-core GEMMs)
    gemm_tf32<<<ggrid, 256>>>(X, WQw, WQb, 0, nullptr);
    gemm_tf32<<<ggrid, 256>>>(X, WKw, WKb, 1, nullptr);

    // Gram matrix + Frobenius norms -> deterministic partials
    gram_kernel<<<GRAM_CTAS, 256>>>();

    // Sigmoid + dual softmax + 10 projection iterations -> P, colsums
    finalize_kernel<<<1, 256>>>();

    // Y = P^T-mixed X (V is never materialized)
    mix_kernel<<<NPER4 / 256, 256>>>(X);

    // final = Y @ WV^T + colsum_j * bV
    gemm_tf32<<<ggrid, 256>>>(nullptr, WVw, WVb, 2, out);
}

// round 4
// speedup vs baseline: 1.3477x; 1.3477x over previous
#include <cuda_runtime.h>
#include <cstdint>
#include <math.h>

// Problem dims
#define M_DIM 16
#define VN    8192
#define DIN   512
#define DOUT  512
#define ROWS  (M_DIM * VN)              // 131072
#define NPER  (VN * DIN)                // 4194304 per m-slice
#define NPER4 (NPER / 4)

#define GRAM_CTAS   1024
#define PART_STRIDE 272                 // 256 G partials + 16 sq partials

// -------------------- scratch --------------------
__device__ float g_U[(size_t)ROWS * DOUT];          // U = X Wv^T + bv
__device__ float g_part[GRAM_CTAS * PART_STRIDE];
__device__ float g_P[256];

// -------------------- helpers --------------------
__device__ __forceinline__ uint32_t f2tf(float f) {
    uint32_t u;
    asm("cvt.rna.tf32.f32 %0, %1;" : "=r"(u) : "f"(f));
    return u;
}

__device__ __forceinline__ void mma_tf32(float c[4], const uint32_t a[4],
                                         uint32_t b0, uint32_t b1) {
    asm volatile(
        "mma.sync.aligned.m16n8k8.row.col.f32.tf32.tf32.f32 "
        "{%0,%1,%2,%3}, {%4,%5,%6,%7}, {%8,%9}, {%0,%1,%2,%3};\n"
        : "+f"(c[0]), "+f"(c[1]), "+f"(c[2]), "+f"(c[3])
        : "r"(a[0]), "r"(a[1]), "r"(a[2]), "r"(a[3]), "r"(b0), "r"(b1));
}

__device__ __forceinline__ uint32_t sptr(const void* p) {
    return (uint32_t)__cvta_generic_to_shared(p);
}
__device__ __forceinline__ void cpa16(uint32_t s, const void* g) {
    asm volatile("cp.async.ca.shared.global [%0], [%1], 16;\n" :: "r"(s), "l"(g));
}
#define CP_COMMIT()  asm volatile("cp.async.commit_group;\n")
#define CP_WAIT1()   asm volatile("cp.async.wait_group 1;\n")
#define CP_WAIT0()   asm volatile("cp.async.wait_group 0;\n")

// ============================================================================
// K1: fused QK projections + Gram + fro. Q/K never hit HBM.
// Grid: 1024 CTAs, CTA = 8 v's x all 16 m-slices (128 gathered rows).
// For each 128-col tile: 2-stage cp.async tf32 GEMM (Q and K accumulators),
// epilogue stages Q/K tiles (+bias) to smem, gram contraction via MMAs
// (warp w handles v-offset w), scalar ||Q||^2 pass.
// Dynamic smem union:
//   pipeline: 2 stages x (A[128x36] + Bq[128x36] + Bk[128x36])  = 27648 f
//   gram:     QT[128x133] + KT[128x133]                          = 34048 f
//   extra:    RED[8x256] + RED2[256]                             =  2304 f
// ============================================================================
#define K1_QT_OFF    0
#define K1_KT_OFF    17024
#define K1_RED_OFF   34048
#define K1_FLOATS    (34048 + 2304)
#define K1_BYTES     (K1_FLOATS * 4)

__global__ void __launch_bounds__(256) qkgram_kernel(
    const float* __restrict__ X,
    const float* __restrict__ Wq, const float* __restrict__ biasq,
    const float* __restrict__ Wk, const float* __restrict__ biask)
{
    extern __shared__ float S[];
    float* QT = S + K1_QT_OFF;      // 128 x 133
    float* KT = S + K1_KT_OFF;      // 128 x 133

    const int tid  = threadIdx.x;
    const int lane = tid & 31;
    const int wid  = tid >> 5;      // 0..7; also the dv this warp handles in gram
    const int gid  = lane >> 2;     // 0..7
    const int tig  = lane & 3;      // 0..3
    const int wm   = wid & 3;
    const int wn   = wid >> 2;
    const int v0   = blockIdx.x * 8;

    float Gc[2][4] = {{0.f,0.f,0.f,0.f},{0.f,0.f,0.f,0.f}};
    float facc = 0.f;
    float Qa[2][8][4], Ka[2][8][4];

    for (int ct = 0; ct < 4; ++ct) {
        const int n0 = ct * 128;
#pragma unroll
        for (int a = 0; a < 2; a++)
#pragma unroll
            for (int b = 0; b < 8; b++)
#pragma unroll
                for (int c = 0; c < 4; c++) { Qa[a][b][c] = 0.f; Ka[a][b][c] = 0.f; }

        auto issue = [&](int kt, int st) {
            float* dstA = S + st * 13824;
#pragma unroll
            for (int it = 0; it < 4; ++it) {
                int idx = tid + it * 256;
                int r   = idx >> 3;
                int c4  = (idx & 7) << 2;
                int grow = (r >> 3) * VN + v0 + (r & 7);   // gathered (i, v)
                uint32_t sA = sptr(dstA + r * 36 + c4);
                cpa16(sA,             X  + (size_t)grow * DIN       + kt * 32 + c4);
                cpa16(sA + 4608 * 4,  Wq + (size_t)(n0 + r) * DIN   + kt * 32 + c4);
                cpa16(sA + 9216 * 4,  Wk + (size_t)(n0 + r) * DIN   + kt * 32 + c4);
            }
        };

        issue(0, 0); CP_COMMIT();
#pragma unroll 1
        for (int kt = 0; kt < 16; ++kt) {
            if (kt < 15) { issue(kt + 1, (kt + 1) & 1); CP_COMMIT(); CP_WAIT1(); }
            else         { CP_WAIT0(); }
            __syncthreads();
            const float* SA  = S + (kt & 1) * 13824;
            const float* SBq = SA + 4608;
            const float* SBk = SA + 9216;
#pragma unroll
            for (int ks = 0; ks < 4; ++ks) {
                const int kb = ks * 8;
                uint32_t af[2][4];
#pragma unroll
                for (int mf = 0; mf < 2; ++mf) {
                    int rb = wm * 32 + mf * 16;
                    af[mf][0] = f2tf(SA[(rb + gid)     * 36 + kb + tig]);
                    af[mf][1] = f2tf(SA[(rb + gid + 8) * 36 + kb + tig]);
                    af[mf][2] = f2tf(SA[(rb + gid)     * 36 + kb + tig + 4]);
                    af[mf][3] = f2tf(SA[(rb + gid + 8) * 36 + kb + tig + 4]);
                }
#pragma unroll
                for (int nf = 0; nf < 8; ++nf) {
                    int nb = wn * 64 + nf * 8;
                    uint32_t q0 = f2tf(SBq[(nb + gid) * 36 + kb + tig]);
                    uint32_t q1 = f2tf(SBq[(nb + gid) * 36 + kb + tig + 4]);
                    mma_tf32(Qa[0][nf], af[0], q0, q1);
                    mma_tf32(Qa[1][nf], af[1], q0, q1);
                    uint32_t k0 = f2tf(SBk[(nb + gid) * 36 + kb + tig]);
                    uint32_t k1 = f2tf(SBk[(nb + gid) * 36 + kb + tig + 4]);
                    mma_tf32(Ka[0][nf], af[0], k0, k1);
                    mma_tf32(Ka[1][nf], af[1], k0, k1);
                }
            }
            __syncthreads();
        }

        // Epilogue: stage Q/K tiles (+bias) into smem (union with pipeline bufs)
#pragma unroll
        for (int nf = 0; nf < 8; ++nf) {
            int col = wn * 64 + nf * 8 + tig * 2;
            float bq0 = biasq[n0 + col], bq1 = biasq[n0 + col + 1];
            float bk0 = biask[n0 + col], bk1 = biask[n0 + col + 1];
#pragma unroll
            for (int mf = 0; mf < 2; ++mf) {
                int r0 = wm * 32 + mf * 16 + gid;
                QT[r0 * 133 + col]           = Qa[mf][nf][0] + bq0;
                QT[r0 * 133 + col + 1]       = Qa[mf][nf][1] + bq1;
                QT[(r0 + 8) * 133 + col]     = Qa[mf][nf][2] + bq0;
                QT[(r0 + 8) * 133 + col + 1] = Qa[mf][nf][3] + bq1;
                KT[r0 * 133 + col]           = Ka[mf][nf][0] + bk0;
                KT[r0 * 133 + col + 1]       = Ka[mf][nf][1] + bk1;
                KT[(r0 + 8) * 133 + col]     = Ka[mf][nf][2] + bk0;
                KT[(r0 + 8) * 133 + col + 1] = Ka[mf][nf][3] + bk1;
            }
        }
        __syncthreads();

        // Gram via MMA: warp `wid` handles dv=wid. G[i,j] += Q[i,dv,:] . K[j,dv,:]
#pragma unroll
        for (int kk = 0; kk < 16; ++kk) {
            const int kb = kk * 8 + tig;
            uint32_t a[4];
            a[0] = f2tf(QT[(gid * 8 + wid)       * 133 + kb]);
            a[1] = f2tf(QT[((gid + 8) * 8 + wid) * 133 + kb]);
            a[2] = f2tf(QT[(gid * 8 + wid)       * 133 + kb + 4]);
            a[3] = f2tf(QT[((gid + 8) * 8 + wid) * 133 + kb + 4]);
            uint32_t b0 = f2tf(KT[(gid * 8 + wid) * 133 + kb]);
            uint32_t b1 = f2tf(KT[(gid * 8 + wid) * 133 + kb + 4]);
            mma_tf32(Gc[0], a, b0, b1);
            b0 = f2tf(KT[((gid + 8) * 8 + wid) * 133 + kb]);
            b1 = f2tf(KT[((gid + 8) * 8 + wid) * 133 + kb + 4]);
            mma_tf32(Gc[1], a, b0, b1);
        }

        // fro: ||Q||^2 partial (row r, half h)
        {
            int r = tid >> 1, cb = (tid & 1) * 64;
#pragma unroll 8
            for (int c = 0; c < 64; ++c) {
                float v = QT[r * 133 + cb + c];
                facc += v * v;
            }
        }
        __syncthreads();
    }

    // Reduce gram fragments across warps -> per-CTA partial
    float* RED = S + K1_RED_OFF;
    RED[wid * 256 + gid * 16 + 2 * tig]               = Gc[0][0];
    RED[wid * 256 + gid * 16 + 2 * tig + 1]           = Gc[0][1];
    RED[wid * 256 + (gid + 8) * 16 + 2 * tig]         = Gc[0][2];
    RED[wid * 256 + (gid + 8) * 16 + 2 * tig + 1]     = Gc[0][3];
    RED[wid * 256 + gid * 16 + 8 + 2 * tig]           = Gc[1][0];
    RED[wid * 256 + gid * 16 + 8 + 2 * tig + 1]       = Gc[1][1];
    RED[wid * 256 + (gid + 8) * 16 + 8 + 2 * tig]     = Gc[1][2];
    RED[wid * 256 + (gid + 8) * 16 + 8 + 2 * tig + 1] = Gc[1][3];
    __syncthreads();
    float g = 0.f;
#pragma unroll
    for (int w = 0; w < 8; ++w) g += RED[w * 256 + tid];
    g_part[(size_t)blockIdx.x * PART_STRIDE + tid] = g;

    float* RED2 = RED + 2048;
    RED2[tid] = facc;
    __syncthreads();
    if (tid < 16) {
        float s = 0.f;
#pragma unroll
        for (int t = 0; t < 16; ++t) s += RED2[tid * 16 + t];
        g_part[(size_t)blockIdx.x * PART_STRIDE + 256 + tid] = s;
    }
}

// ============================================================================
// K2: U = X Wv^T + bv  (tf32, 128x128 tiles, k-tile 16, 2-stage cp.async,
// static smem 40KB -> 2 CTAs/SM)
// ============================================================================
__global__ void __launch_bounds__(256) gemm_v(
    const float* __restrict__ X, const float* __restrict__ W,
    const float* __restrict__ bias)
{
    __shared__ float S[2 * 5120];   // stage: A[128x20] + B[128x20]

    const int tid  = threadIdx.x;
    const int lane = tid & 31;
    const int wid  = tid >> 5;
    const int gid  = lane >> 2;
    const int tig  = lane & 3;
    const int wm   = wid & 3;
    const int wn   = wid >> 2;
    const int m0   = blockIdx.y * 128;
    const int n0   = blockIdx.x * 128;

    float acc[2][8][4];
#pragma unroll
    for (int a = 0; a < 2; a++)
#pragma unroll
        for (int b = 0; b < 8; b++)
#pragma unroll
            for (int c = 0; c < 4; c++) acc[a][b][c] = 0.f;

    auto issue = [&](int kt, int st) {
        float* dst = S + st * 5120;
#pragma unroll
        for (int it = 0; it < 2; ++it) {
            int idx = tid + it * 256;
            int r   = idx >> 2;
            int c4  = (idx & 3) << 2;
            uint32_t sA = sptr(dst + r * 20 + c4);
            cpa16(sA,            X + (size_t)(m0 + r) * DIN + kt * 16 + c4);
            cpa16(sA + 2560 * 4, W + (size_t)(n0 + r) * DIN + kt * 16 + c4);
        }
    };

    issue(0, 0); CP_COMMIT();
#pragma unroll 1
    for (int kt = 0; kt < 32; ++kt) {
        if (kt < 31) { issue(kt + 1, (kt + 1) & 1); CP_COMMIT(); CP_WAIT1(); }
        else         { CP_WAIT0(); }
        __syncthreads();
        const float* SA = S + (kt & 1) * 5120;
        const float* SB = SA + 2560;
#pragma unroll
        for (int ks = 0; ks < 2; ++ks) {
            const int kb = ks * 8;
            uint32_t af[2][4];
#pragma unroll
            for (int mf = 0; mf < 2; ++mf) {
                int rb = wm * 32 + mf * 16;
                af[mf][0] = f2tf(SA[(rb + gid)     * 20 + kb + tig]);
                af[mf][1] = f2tf(SA[(rb + gid + 8) * 20 + kb + tig]);
                af[mf][2] = f2tf(SA[(rb + gid)     * 20 + kb + tig + 4]);
                af[mf][3] = f2tf(SA[(rb + gid + 8) * 20 + kb + tig + 4]);
            }
#pragma unroll
            for (int nf = 0; nf < 8; ++nf) {
                int nb = wn * 64 + nf * 8;
                uint32_t b0 = f2tf(SB[(nb + gid) * 20 + kb + tig]);
                uint32_t b1 = f2tf(SB[(nb + gid) * 20 + kb + tig + 4]);
                mma_tf32(acc[0][nf], af[0], b0, b1);
                mma_tf32(acc[1][nf], af[1], b0, b1);
            }
        }
        __syncthreads();
    }

#pragma unroll
    for (int nf = 0; nf < 8; ++nf) {
        int col = n0 + wn * 64 + nf * 8 + tig * 2;
        float b0 = bias[col];
        float b1 = bias[col + 1];
#pragma unroll
        for (int mf = 0; mf < 2; ++mf) {
            int r0 = m0 + wm * 32 + mf * 16 + gid;
            *(float2*)(g_U + (size_t)r0 * DOUT + col) =
                make_float2(acc[mf][nf][0] + b0, acc[mf][nf][1] + b1);
            *(float2*)(g_U + (size_t)(r0 + 8) * DOUT + col) =
                make_float2(acc[mf][nf][2] + b0, acc[mf][nf][3] + b1);
        }
    }
}

// ============================================================================
// K3: finalize — reduce partials, sigmoid, dual softmax, 10x projection -> P
// ============================================================================
__global__ void __launch_bounds__(256) finalize_kernel()
{
    __shared__ float Am[256], T[256], FR[256];
    __shared__ float fro[16], m0s[16], s0s[16], m1s[16], s1s[16], red[16], red2[16];
    const int tid = threadIdx.x;
    const int i = tid >> 4, j = tid & 15;

    // G partial reduction, 8-way ILP
    float a0=0,a1=0,a2=0,a3=0,a4=0,a5=0,a6=0,a7=0;
    for (int c = 0; c < GRAM_CTAS; c += 8) {
        a0 += g_part[(size_t)(c    ) * PART_STRIDE + tid];
        a1 += g_part[(size_t)(c + 1) * PART_STRIDE + tid];
        a2 += g_part[(size_t)(c + 2) * PART_STRIDE + tid];
        a3 += g_part[(size_t)(c + 3) * PART_STRIDE + tid];
        a4 += g_part[(size_t)(c + 4) * PART_STRIDE + tid];
        a5 += g_part[(size_t)(c + 5) * PART_STRIDE + tid];
        a6 += g_part[(size_t)(c + 6) * PART_STRIDE + tid];
        a7 += g_part[(size_t)(c + 7) * PART_STRIDE + tid];
    }
    float g = ((a0 + a1) + (a2 + a3)) + ((a4 + a5) + (a6 + a7));

    // fro partials: 256 threads cooperate (16 chunks x 16 slices)
    {
        float s = 0.f;
        for (int c = i * 64; c < i * 64 + 64; ++c)
            s += g_part[(size_t)c * PART_STRIDE + 256 + j];
        FR[tid] = s;
    }
    __syncthreads();
    if (tid < 16) {
        float s = 0.f;
#pragma unroll
        for (int t = 0; t < 16; ++t) s += FR[t * 16 + tid];
        fro[tid] = sqrtf(s);
    }
    __syncthreads();

    // P0 = sigmoid(G_raw / fro_i)   (nq == 1 analytically)
    float p0 = 1.f / (1.f + expf(-g / fro[i]));
    Am[tid] = p0;
    __syncthreads();

    if (tid < 16) {
        float m = -1e30f;
        for (int k = 0; k < 16; ++k) m = fmaxf(m, Am[k * 16 + tid]);
        float s = 0.f;
        for (int k = 0; k < 16; ++k) s += expf(Am[k * 16 + tid] - m);
        m0s[tid] = m; s0s[tid] = s;
        float m1 = -1e30f;
        for (int k = 0; k < 16; ++k) m1 = fmaxf(m1, Am[tid * 16 + k]);
        float s1 = 0.f;
        for (int k = 0; k < 16; ++k) s1 += expf(Am[tid * 16 + k] - m1);
        m1s[tid] = m1; s1s[tid] = s1;
    }
    __syncthreads();

    float p = 0.5f * (expf(p0 - m0s[j]) / s0s[j] + expf(p0 - m1s[i]) / s1s[i]);

    for (int it = 0; it < 10; ++it) {
        float p1 = fmaxf(p, 0.f);
        T[tid] = p1;
        __syncthreads();
        if (tid < 16) {
            float s = 0.f;
            for (int k = 0; k < 16; ++k) s += T[tid * 16 + k];
            red[tid] = (s - 1.f) * (1.f / 16.f);
        }
        __syncthreads();
        float p2 = p1 - red[i];
        T[tid] = p2;
        __syncthreads();
        if (tid < 16) {
            float s = 0.f;
            for (int k = 0; k < 16; ++k) s += T[k * 16 + tid];
            red2[tid] = (s - 1.f) * (1.f / 16.f);
        }
        __syncthreads();
        p = p2 - red2[j];
        __syncthreads();
    }
    g_P[tid] = p;
}

// ============================================================================
// K4: out[j] = sum_i P[i,j] * U[i]   (bias already inside U)
// ============================================================================
__global__ void __launch_bounds__(256) mix_kernel(float* __restrict__ out)
{
    __shared__ float Ps[256];
    Ps[threadIdx.x] = g_P[threadIdx.x];
    __syncthreads();

    size_t n4 = (size_t)blockIdx.x * 256 + threadIdx.x;
    const float4* U4 = (const float4*)g_U;
    float4* O4 = (float4*)out;

    float4 x[16];
#pragma unroll
    for (int i = 0; i < 16; ++i) x[i] = U4[(size_t)i * NPER4 + n4];
#pragma unroll
    for (int jj = 0; jj < 16; ++jj) {
        float4 y = make_float4(0.f, 0.f, 0.f, 0.f);
#pragma unroll
        for (int i = 0; i < 16; ++i) {
            float pv = Ps[i * 16 + jj];
            y.x += pv * x[i].x; y.y += pv * x[i].y;
            y.z += pv * x[i].z; y.w += pv * x[i].w;
        }
        O4[(size_t)jj * NPER4 + n4] = y;
    }
}

// -------------------- launch --------------------
extern "C" void kernel_launch(void* const* d_in, const int* in_sizes, int n_in,
                              void* d_out, int out_size)
{
    const float* X   = (const float*)d_in[0];
    const float* WQw = (const float*)d_in[1];
    const float* WQb = (const float*)d_in[2];
    const float* WKw = (const float*)d_in[3];
    const float* WKb = (const float*)d_in[4];
    const float* WVw = (const float*)d_in[5];
    const float* WVb = (const float*)d_in[6];
    float* out = (float*)d_out;

    cudaFuncSetAttribute(qkgram_kernel,
                         cudaFuncAttributeMaxDynamicSharedMemorySize, K1_BYTES);

    // Fused Q/K projections + Gram + fro (X read once; Q/K never hit HBM)
    qkgram_kernel<<<GRAM_CTAS, 256, K1_BYTES>>>(X, WQw, WQb, WKw, WKb);

    // U = X Wv^T + bv (independent of P)
    gemm_v<<<dim3(DOUT / 128, ROWS / 128), 256>>>(X, WVw, WVb);

    // P
    finalize_kernel<<<1, 256>>>();

    // out[j] = sum_i P[ij] U[i]
    mix_kernel<<<NPER4 / 256, 256>>>(out);
}

// round 5
// speedup vs baseline: 1.6724x; 1.2410x over previous
#include <cuda_runtime.h>
#include <cstdint>
#include <math.h>

// Problem dims
#define M_DIM 16
#define VN    8192
#define DIN   512
#define DOUT  512
#define ROWS  (M_DIM * VN)              // 131072
#define NPER  (VN * DIN)                // 4194304 per m-slice
#define NPER4 (NPER / 4)

#define GRAM_CTAS   1024
#define PART_STRIDE 272                 // 256 G partials + 16 sq partials

// -------------------- scratch --------------------
__device__ float g_Xt[(size_t)ROWS * DIN];          // tf32-rounded X
__device__ float g_Wq[(size_t)DOUT * DIN];          // tf32-rounded weights
__device__ float g_Wk[(size_t)DOUT * DIN];
__device__ float g_Wv[(size_t)DOUT * DIN];
__device__ float g_U[(size_t)ROWS * DOUT];          // U = X Wv^T + bv
__device__ float g_part[GRAM_CTAS * PART_STRIDE];
__device__ float g_P[256];

// -------------------- helpers --------------------
__device__ __forceinline__ uint32_t f2tf(float f) {
    uint32_t u;
    asm("cvt.rna.tf32.f32 %0, %1;" : "=r"(u) : "f"(f));
    return u;
}

__device__ __forceinline__ void mma_tf32(float c[4], const uint32_t a[4],
                                         uint32_t b0, uint32_t b1) {
    asm volatile(
        "mma.sync.aligned.m16n8k8.row.col.f32.tf32.tf32.f32 "
        "{%0,%1,%2,%3}, {%4,%5,%6,%7}, {%8,%9}, {%0,%1,%2,%3};\n"
        : "+f"(c[0]), "+f"(c[1]), "+f"(c[2]), "+f"(c[3])
        : "r"(a[0]), "r"(a[1]), "r"(a[2]), "r"(a[3]), "r"(b0), "r"(b1));
}

__device__ __forceinline__ uint32_t sptr(const void* p) {
    return (uint32_t)__cvta_generic_to_shared(p);
}
__device__ __forceinline__ void cpa16(uint32_t s, const void* g) {
    asm volatile("cp.async.ca.shared.global [%0], [%1], 16;\n" :: "r"(s), "l"(g));
}
#define CP_COMMIT()  asm volatile("cp.async.commit_group;\n")
#define CP_WAIT1()   asm volatile("cp.async.wait_group 1;\n")
#define CP_WAIT0()   asm volatile("cp.async.wait_group 0;\n")

// ldmatrix: 16B row-chunks; our chunks are 4 consecutive tf32 -> fragment layout
// matches mma m16n8k8 tf32 operands exactly.
__device__ __forceinline__ void ldsm_x4(uint32_t r[4], uint32_t saddr) {
    asm volatile("ldmatrix.sync.aligned.m8n8.x4.shared.b16 {%0,%1,%2,%3}, [%4];"
        : "=r"(r[0]), "=r"(r[1]), "=r"(r[2]), "=r"(r[3]) : "r"(saddr));
}

// -------------------- prep: tf32-round a buffer --------------------
__global__ void prep_kernel(const float4* __restrict__ src,
                            float4* __restrict__ dst, int n4)
{
    int stride = gridDim.x * blockDim.x;
    for (int i = blockIdx.x * blockDim.x + threadIdx.x; i < n4; i += stride) {
        float4 v = src[i];
        uint4 u = make_uint4(f2tf(v.x), f2tf(v.y), f2tf(v.z), f2tf(v.w));
        dst[i] = *(float4*)&u;
    }
}

// ============================================================================
// K1: fused QK projections + Gram + fro. Q/K never hit HBM. All operands
// pre-rounded to tf32 -> NO cvt in inner loop; ldmatrix fragment loads.
// ============================================================================
#define K1_QT_OFF    0
#define K1_KT_OFF    17024
#define K1_RED_OFF   34048
#define K1_FLOATS    (34048 + 2304)
#define K1_BYTES     (K1_FLOATS * 4)

__global__ void __launch_bounds__(256) qkgram_kernel(
    const float* __restrict__ biasq, const float* __restrict__ biask)
{
    extern __shared__ float S[];
    float* QT = S + K1_QT_OFF;      // 128 x 133
    float* KT = S + K1_KT_OFF;      // 128 x 133

    const int tid  = threadIdx.x;
    const int lane = tid & 31;
    const int wid  = tid >> 5;
    const int gid  = lane >> 2;
    const int tig  = lane & 3;
    const int wm   = wid & 3;
    const int wn   = wid >> 2;
    const int v0   = blockIdx.x * 8;

    // ldmatrix per-lane float offset inside a tile (stride 36):
    // matrices: (rows+0..7,kb),(rows+8..15,kb),(rows+0..7,kb+4),(rows+8..15,kb+4)
    const int lrow = lane & 15;
    const int lcol = (lane >> 4) << 2;          // 0 or 4
    const int lofs = lrow * 36 + lcol;          // add (rb*36 + kb)

    float Gc[2][4] = {{0.f,0.f,0.f,0.f},{0.f,0.f,0.f,0.f}};
    float facc = 0.f;
    float Qa[2][8][4], Ka[2][8][4];

    for (int ct = 0; ct < 4; ++ct) {
        const int n0 = ct * 128;
#pragma unroll
        for (int a = 0; a < 2; a++)
#pragma unroll
            for (int b = 0; b < 8; b++)
#pragma unroll
                for (int c = 0; c < 4; c++) { Qa[a][b][c] = 0.f; Ka[a][b][c] = 0.f; }

        auto issue = [&](int kt, int st) {
            float* dstA = S + st * 13824;
#pragma unroll
            for (int it = 0; it < 4; ++it) {
                int idx = tid + it * 256;
                int r   = idx >> 3;
                int c4  = (idx & 7) << 2;
                int grow = (r >> 3) * VN + v0 + (r & 7);   // gathered (i, v)
                uint32_t sA = sptr(dstA + r * 36 + c4);
                cpa16(sA,            g_Xt + (size_t)grow * DIN     + kt * 32 + c4);
                cpa16(sA + 4608 * 4, g_Wq + (size_t)(n0 + r) * DIN + kt * 32 + c4);
                cpa16(sA + 9216 * 4, g_Wk + (size_t)(n0 + r) * DIN + kt * 32 + c4);
            }
        };

        issue(0, 0); CP_COMMIT();
#pragma unroll 1
        for (int kt = 0; kt < 16; ++kt) {
            if (kt < 15) { issue(kt + 1, (kt + 1) & 1); CP_COMMIT(); CP_WAIT1(); }
            else         { CP_WAIT0(); }
            __syncthreads();
            const uint32_t sA  = sptr(S + (kt & 1) * 13824) + lofs * 4;
            const uint32_t sBq = sA + 4608 * 4;
            const uint32_t sBk = sA + 9216 * 4;
#pragma unroll
            for (int ks = 0; ks < 4; ++ks) {
                const int kb4 = ks * 8 * 4;                 // byte offset of kb
                uint32_t af[2][4];
                ldsm_x4(af[0], sA + (wm * 32)      * 144 + kb4);
                ldsm_x4(af[1], sA + (wm * 32 + 16) * 144 + kb4);
#pragma unroll
                for (int p = 0; p < 4; ++p) {
                    const uint32_t nofs = (wn * 64 + p * 16) * 144 + kb4;
                    uint32_t qb[4], kbf[4];
                    ldsm_x4(qb,  sBq + nofs);
                    ldsm_x4(kbf, sBk + nofs);
                    mma_tf32(Qa[0][2*p],     af[0], qb[0],  qb[2]);
                    mma_tf32(Qa[1][2*p],     af[1], qb[0],  qb[2]);
                    mma_tf32(Qa[0][2*p + 1], af[0], qb[1],  qb[3]);
                    mma_tf32(Qa[1][2*p + 1], af[1], qb[1],  qb[3]);
                    mma_tf32(Ka[0][2*p],     af[0], kbf[0], kbf[2]);
                    mma_tf32(Ka[1][2*p],     af[1], kbf[0], kbf[2]);
                    mma_tf32(Ka[0][2*p + 1], af[0], kbf[1], kbf[3]);
                    mma_tf32(Ka[1][2*p + 1], af[1], kbf[1], kbf[3]);
                }
            }
            __syncthreads();
        }

        // Epilogue: stage Q/K tiles (+bias), tf32-rounded, into smem
#pragma unroll
        for (int nf = 0; nf < 8; ++nf) {
            int col = wn * 64 + nf * 8 + tig * 2;
            float bq0 = biasq[n0 + col], bq1 = biasq[n0 + col + 1];
            float bk0 = biask[n0 + col], bk1 = biask[n0 + col + 1];
#pragma unroll
            for (int mf = 0; mf < 2; ++mf) {
                int r0 = wm * 32 + mf * 16 + gid;
                QT[r0 * 133 + col]           = __uint_as_float(f2tf(Qa[mf][nf][0] + bq0));
                QT[r0 * 133 + col + 1]       = __uint_as_float(f2tf(Qa[mf][nf][1] + bq1));
                QT[(r0 + 8) * 133 + col]     = __uint_as_float(f2tf(Qa[mf][nf][2] + bq0));
                QT[(r0 + 8) * 133 + col + 1] = __uint_as_float(f2tf(Qa[mf][nf][3] + bq1));
                KT[r0 * 133 + col]           = __uint_as_float(f2tf(Ka[mf][nf][0] + bk0));
                KT[r0 * 133 + col + 1]       = __uint_as_float(f2tf(Ka[mf][nf][1] + bk1));
                KT[(r0 + 8) * 133 + col]     = __uint_as_float(f2tf(Ka[mf][nf][2] + bk0));
                KT[(r0 + 8) * 133 + col + 1] = __uint_as_float(f2tf(Ka[mf][nf][3] + bk1));
            }
        }
        __syncthreads();

        // Gram via MMA: warp `wid` handles dv=wid. Values already tf32 bits.
#pragma unroll
        for (int kk = 0; kk < 16; ++kk) {
            const int kb = kk * 8 + tig;
            uint32_t a[4];
            a[0] = __float_as_uint(QT[(gid * 8 + wid)       * 133 + kb]);
            a[1] = __float_as_uint(QT[((gid + 8) * 8 + wid) * 133 + kb]);
            a[2] = __float_as_uint(QT[(gid * 8 + wid)       * 133 + kb + 4]);
            a[3] = __float_as_uint(QT[((gid + 8) * 8 + wid) * 133 + kb + 4]);
            uint32_t b0 = __float_as_uint(KT[(gid * 8 + wid) * 133 + kb]);
            uint32_t b1 = __float_as_uint(KT[(gid * 8 + wid) * 133 + kb + 4]);
            mma_tf32(Gc[0], a, b0, b1);
            b0 = __float_as_uint(KT[((gid + 8) * 8 + wid) * 133 + kb]);
            b1 = __float_as_uint(KT[((gid + 8) * 8 + wid) * 133 + kb + 4]);
            mma_tf32(Gc[1], a, b0, b1);
        }

        // fro: ||Q||^2 partial
        {
            int r = tid >> 1, cb = (tid & 1) * 64;
#pragma unroll 8
            for (int c = 0; c < 64; ++c) {
                float v = QT[r * 133 + cb + c];
                facc += v * v;
            }
        }
        __syncthreads();
    }

    // Reduce gram fragments across warps -> per-CTA partial
    float* RED = S + K1_RED_OFF;
    RED[wid * 256 + gid * 16 + 2 * tig]               = Gc[0][0];
    RED[wid * 256 + gid * 16 + 2 * tig + 1]           = Gc[0][1];
    RED[wid * 256 + (gid + 8) * 16 + 2 * tig]         = Gc[0][2];
    RED[wid * 256 + (gid + 8) * 16 + 2 * tig + 1]     = Gc[0][3];
    RED[wid * 256 + gid * 16 + 8 + 2 * tig]           = Gc[1][0];
    RED[wid * 256 + gid * 16 + 8 + 2 * tig + 1]       = Gc[1][1];
    RED[wid * 256 + (gid + 8) * 16 + 8 + 2 * tig]     = Gc[1][2];
    RED[wid * 256 + (gid + 8) * 16 + 8 + 2 * tig + 1] = Gc[1][3];
    __syncthreads();
    float g = 0.f;
#pragma unroll
    for (int w = 0; w < 8; ++w) g += RED[w * 256 + tid];
    g_part[(size_t)blockIdx.x * PART_STRIDE + tid] = g;

    float* RED2 = RED + 2048;
    RED2[tid] = facc;
    __syncthreads();
    if (tid < 16) {
        float s = 0.f;
#pragma unroll
        for (int t = 0; t < 16; ++t) s += RED2[tid * 16 + t];
        g_part[(size_t)blockIdx.x * PART_STRIDE + 256 + tid] = s;
    }
}

// ============================================================================
// K2: U = X Wv^T + bv  (pre-rounded operands, ldmatrix, no cvt)
// ============================================================================
__global__ void __launch_bounds__(256) gemm_v(const float* __restrict__ bias)
{
    __shared__ float S[2 * 5120];   // stage: A[128x20] + B[128x20]

    const int tid  = threadIdx.x;
    const int lane = tid & 31;
    const int wid  = tid >> 5;
    const int gid  = lane >> 2;
    const int tig  = lane & 3;
    const int wm   = wid & 3;
    const int wn   = wid >> 2;
    const int m0   = blockIdx.y * 128;
    const int n0   = blockIdx.x * 128;

    const int lrow = lane & 15;
    const int lcol = (lane >> 4) << 2;
    const int lofs = lrow * 20 + lcol;

    float acc[2][8][4];
#pragma unroll
    for (int a = 0; a < 2; a++)
#pragma unroll
        for (int b = 0; b < 8; b++)
#pragma unroll
            for (int c = 0; c < 4; c++) acc[a][b][c] = 0.f;

    auto issue = [&](int kt, int st) {
        float* dst = S + st * 5120;
#pragma unroll
        for (int it = 0; it < 2; ++it) {
            int idx = tid + it * 256;
            int r   = idx >> 2;
            int c4  = (idx & 3) << 2;
            uint32_t sA = sptr(dst + r * 20 + c4);
            cpa16(sA,            g_Xt + (size_t)(m0 + r) * DIN + kt * 16 + c4);
            cpa16(sA + 2560 * 4, g_Wv + (size_t)(n0 + r) * DIN + kt * 16 + c4);
        }
    };

    issue(0, 0); CP_COMMIT();
#pragma unroll 1
    for (int kt = 0; kt < 32; ++kt) {
        if (kt < 31) { issue(kt + 1, (kt + 1) & 1); CP_COMMIT(); CP_WAIT1(); }
        else         { CP_WAIT0(); }
        __syncthreads();
        const uint32_t sA = sptr(S + (kt & 1) * 5120) + lofs * 4;
        const uint32_t sB = sA + 2560 * 4;
#pragma unroll
        for (int ks = 0; ks < 2; ++ks) {
            const int kb4 = ks * 8 * 4;
            uint32_t af[2][4];
            ldsm_x4(af[0], sA + (wm * 32)      * 80 + kb4);
            ldsm_x4(af[1], sA + (wm * 32 + 16) * 80 + kb4);
#pragma unroll
            for (int p = 0; p < 4; ++p) {
                uint32_t bb[4];
                ldsm_x4(bb, sB + (wn * 64 + p * 16) * 80 + kb4);
                mma_tf32(acc[0][2*p],     af[0], bb[0], bb[2]);
                mma_tf32(acc[1][2*p],     af[1], bb[0], bb[2]);
                mma_tf32(acc[0][2*p + 1], af[0], bb[1], bb[3]);
                mma_tf32(acc[1][2*p + 1], af[1], bb[1], bb[3]);
            }
        }
        __syncthreads();
    }

#pragma unroll
    for (int nf = 0; nf < 8; ++nf) {
        int col = n0 + wn * 64 + nf * 8 + tig * 2;
        float b0 = bias[col];
        float b1 = bias[col + 1];
#pragma unroll
        for (int mf = 0; mf < 2; ++mf) {
            int r0 = m0 + wm * 32 + mf * 16 + gid;
            *(float2*)(g_U + (size_t)r0 * DOUT + col) =
                make_float2(acc[mf][nf][0] + b0, acc[mf][nf][1] + b1);
            *(float2*)(g_U + (size_t)(r0 + 8) * DOUT + col) =
                make_float2(acc[mf][nf][2] + b0, acc[mf][nf][3] + b1);
        }
    }
}

// ============================================================================
// K3: finalize — reduce partials, sigmoid, dual softmax, 10x projection -> P
// ============================================================================
__global__ void __launch_bounds__(256) finalize_kernel()
{
    __shared__ float Am[256], T[256], FR[256];
    __shared__ float fro[16], m0s[16], s0s[16], m1s[16], s1s[16], red[16], red2[16];
    const int tid = threadIdx.x;
    const int i = tid >> 4, j = tid & 15;

    float a0=0,a1=0,a2=0,a3=0,a4=0,a5=0,a6=0,a7=0;
    for (int c = 0; c < GRAM_CTAS; c += 8) {
        a0 += g_part[(size_t)(c    ) * PART_STRIDE + tid];
        a1 += g_part[(size_t)(c + 1) * PART_STRIDE + tid];
        a2 += g_part[(size_t)(c + 2) * PART_STRIDE + tid];
        a3 += g_part[(size_t)(c + 3) * PART_STRIDE + tid];
        a4 += g_part[(size_t)(c + 4) * PART_STRIDE + tid];
        a5 += g_part[(size_t)(c + 5) * PART_STRIDE + tid];
        a6 += g_part[(size_t)(c + 6) * PART_STRIDE + tid];
        a7 += g_part[(size_t)(c + 7) * PART_STRIDE + tid];
    }
    float g = ((a0 + a1) + (a2 + a3)) + ((a4 + a5) + (a6 + a7));

    {
        float s = 0.f;
        for (int c = i * 64; c < i * 64 + 64; ++c)
            s += g_part[(size_t)c * PART_STRIDE + 256 + j];
        FR[tid] = s;
    }
    __syncthreads();
    if (tid < 16) {
        float s = 0.f;
#pragma unroll
        for (int t = 0; t < 16; ++t) s += FR[t * 16 + tid];
        fro[tid] = sqrtf(s);
    }
    __syncthreads();

    float p0 = 1.f / (1.f + expf(-g / fro[i]));
    Am[tid] = p0;
    __syncthreads();

    if (tid < 16) {
        float m = -1e30f;
        for (int k = 0; k < 16; ++k) m = fmaxf(m, Am[k * 16 + tid]);
        float s = 0.f;
        for (int k = 0; k < 16; ++k) s += expf(Am[k * 16 + tid] - m);
        m0s[tid] = m; s0s[tid] = s;
        float m1 = -1e30f;
        for (int k = 0; k < 16; ++k) m1 = fmaxf(m1, Am[tid * 16 + k]);
        float s1 = 0.f;
        for (int k = 0; k < 16; ++k) s1 += expf(Am[tid * 16 + k] - m1);
        m1s[tid] = m1; s1s[tid] = s1;
    }
    __syncthreads();

    float p = 0.5f * (expf(p0 - m0s[j]) / s0s[j] + expf(p0 - m1s[i]) / s1s[i]);

    for (int it = 0; it < 10; ++it) {
        float p1 = fmaxf(p, 0.f);
        T[tid] = p1;
        __syncthreads();
        if (tid < 16) {
            float s = 0.f;
            for (int k = 0; k < 16; ++k) s += T[tid * 16 + k];
            red[tid] = (s - 1.f) * (1.f / 16.f);
        }
        __syncthreads();
        float p2 = p1 - red[i];
        T[tid] = p2;
        __syncthreads();
        if (tid < 16) {
            float s = 0.f;
            for (int k = 0; k < 16; ++k) s += T[k * 16 + tid];
            red2[tid] = (s - 1.f) * (1.f / 16.f);
        }
        __syncthreads();
        p = p2 - red2[j];
        __syncthreads();
    }
    g_P[tid] = p;
}

// ============================================================================
// K4: out[j] = sum_i P[i,j] * U[i]
// ============================================================================
__global__ void __launch_bounds__(256) mix_kernel(float* __restrict__ out)
{
    __shared__ float Ps[256];
    Ps[threadIdx.x] = g_P[threadIdx.x];
    __syncthreads();

    size_t n4 = (size_t)blockIdx.x * 256 + threadIdx.x;
    const float4* U4 = (const float4*)g_U;
    float4* O4 = (float4*)out;

    float4 x[16];
#pragma unroll
    for (int i = 0; i < 16; ++i) x[i] = U4[(size_t)i * NPER4 + n4];
#pragma unroll
    for (int jj = 0; jj < 16; ++jj) {
        float4 y = make_float4(0.f, 0.f, 0.f, 0.f);
#pragma unroll
        for (int i = 0; i < 16; ++i) {
            float pv = Ps[i * 16 + jj];
            y.x += pv * x[i].x; y.y += pv * x[i].y;
            y.z += pv * x[i].z; y.w += pv * x[i].w;
        }
        O4[(size_t)jj * NPER4 + n4] = y;
    }
}

// -------------------- launch --------------------
extern "C" void kernel_launch(void* const* d_in, const int* in_sizes, int n_in,
                              void* d_out, int out_size)
{
    const float* X   = (const float*)d_in[0];
    const float* WQw = (const float*)d_in[1];
    const float* WQb = (const float*)d_in[2];
    const float* WKw = (const float*)d_in[3];
    const float* WKb = (const float*)d_in[4];
    const float* WVw = (const float*)d_in[5];
    const float* WVb = (const float*)d_in[6];
    float* out = (float*)d_out;

    cudaFuncSetAttribute(qkgram_kernel,
                         cudaFuncAttributeMaxDynamicSharedMemorySize, K1_BYTES);

    // Pre-round operands to tf32 (removes ALL cvt from GEMM inner loops)
    float *dXt, *dWq, *dWk, *dWv;
    cudaGetSymbolAddress((void**)&dXt, g_Xt);
    cudaGetSymbolAddress((void**)&dWq, g_Wq);
    cudaGetSymbolAddress((void**)&dWk, g_Wk);
    cudaGetSymbolAddress((void**)&dWv, g_Wv);
    prep_kernel<<<8192, 256>>>((const float4*)X,   (float4*)dXt, ROWS * DIN / 4);
    prep_kernel<<<256, 256>>>((const float4*)WQw, (float4*)dWq, DOUT * DIN / 4);
    prep_kernel<<<256, 256>>>((const float4*)WKw, (float4*)dWk, DOUT * DIN / 4);
    prep_kernel<<<256, 256>>>((const float4*)WVw, (float4*)dWv, DOUT * DIN / 4);

    // Fused Q/K projections + Gram + fro
    qkgram_kernel<<<GRAM_CTAS, 256, K1_BYTES>>>(WQb, WKb);

    // U = X Wv^T + bv
    gemm_v<<<dim3(DOUT / 128, ROWS / 128), 256>>>(WVb);

    // P
    finalize_kernel<<<1, 256>>>();

    // out[j] = sum_i P[ij] U[i]
    mix_kernel<<<NPER4 / 256, 256>>>(out);
}